// round 1
// baseline (speedup 1.0000x reference)
#include <cuda_runtime.h>
#include <math.h>

#define N_TOK 4096
#define CDIM 256
#define HEADS 16
#define DHEAD 64
#define HD 1024
#define NQ 64
#define NKEY 256
#define NTRUNK 64
#define PADL 96

// Scratch (device globals; no allocation allowed)
__device__ float g_q[HEADS * N_TOK * DHEAD];   // [h][n][d], pre-scaled by 1/sqrt(D)
__device__ float g_k[HEADS * N_TOK * DHEAD];   // [h][n][d]
__device__ float g_v[HEADS * N_TOK * DHEAD];   // [h][n][d]
__device__ float g_gate[N_TOK * HD];           // sigmoid(q_x @ Wg), [n][c]
__device__ float g_o[N_TOK * HD];              // attention output, [n][c]

// ---------------------------------------------------------------------------
// Kernel 1: projections. C = A @ W for 4 weight matrices (grid.z selects).
// BM=BN=64, BK=16, 256 threads, 4x4 microtile per thread.
// ---------------------------------------------------------------------------
__global__ __launch_bounds__(256) void proj_kernel(
    const float* __restrict__ qx, const float* __restrict__ kvx,
    const float* __restrict__ Wq, const float* __restrict__ Wk,
    const float* __restrict__ Wv, const float* __restrict__ Wg)
{
    const int mat = blockIdx.z;
    const float* __restrict__ A = (mat == 1 || mat == 2) ? kvx : qx;
    const float* __restrict__ W = (mat == 0) ? Wq : (mat == 1) ? Wk : (mat == 2) ? Wv : Wg;

    __shared__ __align__(16) float As[64][17];   // [m][k], pad to kill bank conflicts
    __shared__ __align__(16) float Bs[16][64];   // [k][n]

    const int tid = threadIdx.x;
    const int tx = tid & 15, ty = tid >> 4;
    const int m0 = blockIdx.y * 64, n0 = blockIdx.x * 64;

    float acc[4][4] = {};

    for (int k0 = 0; k0 < CDIM; k0 += 16) {
        // Load A tile: 64 rows x 16 cols, float4 per thread
        {
            int row = tid >> 2, cg = (tid & 3) * 4;
            float4 a4 = *reinterpret_cast<const float4*>(&A[(m0 + row) * CDIM + k0 + cg]);
            As[row][cg + 0] = a4.x; As[row][cg + 1] = a4.y;
            As[row][cg + 2] = a4.z; As[row][cg + 3] = a4.w;
            // Load B tile: 16 rows x 64 cols
            int kk = tid >> 4, ng = (tid & 15) * 4;
            *reinterpret_cast<float4*>(&Bs[kk][ng]) =
                *reinterpret_cast<const float4*>(&W[(k0 + kk) * HD + n0 + ng]);
        }
        __syncthreads();
        #pragma unroll
        for (int kk = 0; kk < 16; kk++) {
            float aq[4];
            #pragma unroll
            for (int i = 0; i < 4; i++) aq[i] = As[ty * 4 + i][kk];
            float4 b4 = *reinterpret_cast<float4*>(&Bs[kk][tx * 4]);
            float bq[4] = {b4.x, b4.y, b4.z, b4.w};
            #pragma unroll
            for (int i = 0; i < 4; i++)
                #pragma unroll
                for (int j = 0; j < 4; j++) acc[i][j] += aq[i] * bq[j];
        }
        __syncthreads();
    }

    #pragma unroll
    for (int i = 0; i < 4; i++) {
        int r = m0 + ty * 4 + i;
        #pragma unroll
        for (int j = 0; j < 4; j++) {
            int c = n0 + tx * 4 + j;
            float val = acc[i][j];
            int h = c / DHEAD, d = c % DHEAD;
            if (mat == 0)      g_q[h * N_TOK * DHEAD + r * DHEAD + d] = val * 0.125f;
            else if (mat == 1) g_k[h * N_TOK * DHEAD + r * DHEAD + d] = val;
            else if (mat == 2) g_v[h * N_TOK * DHEAD + r * DHEAD + d] = val;
            else               g_gate[r * HD + c] = 1.f / (1.f + expf(-val));
        }
    }
}

// ---------------------------------------------------------------------------
// Kernel 2: local attention. One block per (trunk, head). 256 threads.
// Trunk t: queries [t*64, t*64+64), keys at global indices t*64-96+j, j<256.
// Out-of-range keys: k=0, v=0, bias=0 -> score exactly 0, still in softmax.
// Dynamic smem: qs[64][65] + ks[64][65] + sc[64][256]  (= 98816 B)
// ---------------------------------------------------------------------------
__global__ __launch_bounds__(256) void attn_kernel(const float* __restrict__ bias)
{
    extern __shared__ float smem[];
    float (*qs)[65] = (float(*)[65])smem;                  // 64*65
    float (*ks)[65] = (float(*)[65])(smem + 64 * 65);      // 64*65 (reused for v)
    float (*sc)[NKEY] = (float(*)[NKEY])(smem + 2 * 64 * 65);

    const int t = blockIdx.x, h = blockIdx.y;
    const int tid = threadIdx.x;
    const int tx = tid & 15, ty = tid >> 4;
    const int kbase = t * NQ - PADL;

    // Load q tile [64][64]
    const float* qsrc = &g_q[h * N_TOK * DHEAD + t * NQ * DHEAD];
    for (int i = tid; i < NQ * DHEAD; i += 256) qs[i / DHEAD][i % DHEAD] = qsrc[i];

    // ---- scores: 4 key chunks of 64 ----
    for (int kc = 0; kc < 4; kc++) {
        __syncthreads();   // covers qs load (kc=0) and prior ks readers (kc>0)
        for (int i = tid; i < 64 * DHEAD; i += 256) {
            int jj = i / DHEAD, d = i % DHEAD;
            int gk = kbase + kc * 64 + jj;
            ks[jj][d] = (gk >= 0 && gk < N_TOK) ? g_k[h * N_TOK * DHEAD + gk * DHEAD + d] : 0.f;
        }
        __syncthreads();
        float acc[4][4] = {};
        #pragma unroll 16
        for (int d = 0; d < DHEAD; d++) {
            float aq[4], ak[4];
            #pragma unroll
            for (int i = 0; i < 4; i++) aq[i] = qs[ty * 4 + i][d];
            #pragma unroll
            for (int j = 0; j < 4; j++) ak[j] = ks[tx * 4 + j][d];
            #pragma unroll
            for (int i = 0; i < 4; i++)
                #pragma unroll
                for (int j = 0; j < 4; j++) acc[i][j] += aq[i] * ak[j];
        }
        #pragma unroll
        for (int i = 0; i < 4; i++) {
            int qi = ty * 4 + i;
            #pragma unroll
            for (int j = 0; j < 4; j++) {
                int jj = tx * 4 + j;
                int gk = kbase + kc * 64 + jj;
                float b = (gk >= 0 && gk < N_TOK)
                        ? bias[(size_t)(t * NQ + qi) * N_TOK + gk] : 0.f;
                sc[qi][kc * 64 + jj] = acc[i][j] + b;
            }
        }
    }
    __syncthreads();

    // ---- softmax: warp per row, 8 warps ----
    const int wid = tid >> 5, lane = tid & 31;
    for (int r = wid; r < NQ; r += 8) {
        float vals[8];
        float m = -1e30f;
        #pragma unroll
        for (int k = 0; k < 8; k++) { vals[k] = sc[r][lane + 32 * k]; m = fmaxf(m, vals[k]); }
        #pragma unroll
        for (int off = 16; off > 0; off >>= 1) m = fmaxf(m, __shfl_xor_sync(0xffffffffu, m, off));
        float s = 0.f;
        #pragma unroll
        for (int k = 0; k < 8; k++) { vals[k] = expf(vals[k] - m); s += vals[k]; }
        #pragma unroll
        for (int off = 16; off > 0; off >>= 1) s += __shfl_xor_sync(0xffffffffu, s, off);
        float inv = 1.f / s;
        #pragma unroll
        for (int k = 0; k < 8; k++) sc[r][lane + 32 * k] = vals[k] * inv;
    }
    __syncthreads();

    // ---- o = w @ v : 4 value chunks of 64 ----
    float oacc[4][4] = {};
    for (int kc = 0; kc < 4; kc++) {
        for (int i = tid; i < 64 * DHEAD; i += 256) {
            int jj = i / DHEAD, d = i % DHEAD;
            int gk = kbase + kc * 64 + jj;
            ks[jj][d] = (gk >= 0 && gk < N_TOK) ? g_v[h * N_TOK * DHEAD + gk * DHEAD + d] : 0.f;
        }
        __syncthreads();
        #pragma unroll 16
        for (int jj = 0; jj < 64; jj++) {
            float w[4], vv[4];
            #pragma unroll
            for (int i = 0; i < 4; i++) w[i] = sc[ty * 4 + i][kc * 64 + jj];
            #pragma unroll
            for (int j = 0; j < 4; j++) vv[j] = ks[jj][tx * 4 + j];
            #pragma unroll
            for (int i = 0; i < 4; i++)
                #pragma unroll
                for (int j = 0; j < 4; j++) oacc[i][j] += w[i] * vv[j];
        }
        __syncthreads();
    }

    #pragma unroll
    for (int i = 0; i < 4; i++) {
        int r = t * NQ + ty * 4 + i;
        #pragma unroll
        for (int j = 0; j < 4; j++)
            g_o[r * HD + h * DHEAD + tx * 4 + j] = oacc[i][j];
    }
}

// ---------------------------------------------------------------------------
// Kernel 3: out = (o * gate) @ Wo.  M=4096, N=256, K=1024.
// ---------------------------------------------------------------------------
__global__ __launch_bounds__(256) void out_kernel(
    const float* __restrict__ Wo, float* __restrict__ out)
{
    __shared__ __align__(16) float As[64][17];
    __shared__ __align__(16) float Bs[16][64];

    const int tid = threadIdx.x;
    const int tx = tid & 15, ty = tid >> 4;
    const int m0 = blockIdx.y * 64, n0 = blockIdx.x * 64;

    float acc[4][4] = {};

    for (int k0 = 0; k0 < HD; k0 += 16) {
        {
            int row = tid >> 2, cg = (tid & 3) * 4;
            float4 a4 = *reinterpret_cast<const float4*>(&g_o[(size_t)(m0 + row) * HD + k0 + cg]);
            float4 g4 = *reinterpret_cast<const float4*>(&g_gate[(size_t)(m0 + row) * HD + k0 + cg]);
            As[row][cg + 0] = a4.x * g4.x; As[row][cg + 1] = a4.y * g4.y;
            As[row][cg + 2] = a4.z * g4.z; As[row][cg + 3] = a4.w * g4.w;
            int kk = tid >> 4, ng = (tid & 15) * 4;
            *reinterpret_cast<float4*>(&Bs[kk][ng]) =
                *reinterpret_cast<const float4*>(&Wo[(k0 + kk) * CDIM + n0 + ng]);
        }
        __syncthreads();
        #pragma unroll
        for (int kk = 0; kk < 16; kk++) {
            float aq[4];
            #pragma unroll
            for (int i = 0; i < 4; i++) aq[i] = As[ty * 4 + i][kk];
            float4 b4 = *reinterpret_cast<float4*>(&Bs[kk][tx * 4]);
            float bq[4] = {b4.x, b4.y, b4.z, b4.w};
            #pragma unroll
            for (int i = 0; i < 4; i++)
                #pragma unroll
                for (int j = 0; j < 4; j++) acc[i][j] += aq[i] * bq[j];
        }
        __syncthreads();
    }

    #pragma unroll
    for (int i = 0; i < 4; i++) {
        int r = m0 + ty * 4 + i;
        #pragma unroll
        for (int j = 0; j < 4; j++)
            out[(size_t)r * CDIM + n0 + tx * 4 + j] = acc[i][j];
    }
}

// ---------------------------------------------------------------------------
extern "C" void kernel_launch(void* const* d_in, const int* in_sizes, int n_in,
                              void* d_out, int out_size)
{
    const float* qx   = (const float*)d_in[0];
    const float* kvx  = (const float*)d_in[1];
    const float* bias = (const float*)d_in[2];
    const float* Wq   = (const float*)d_in[3];
    const float* Wk   = (const float*)d_in[4];
    const float* Wv   = (const float*)d_in[5];
    const float* Wg   = (const float*)d_in[6];
    const float* Wo   = (const float*)d_in[7];
    float* out = (float*)d_out;

    // 1) projections: grid (HD/64, N/64, 4 matrices)
    proj_kernel<<<dim3(HD / 64, N_TOK / 64, 4), 256>>>(qx, kvx, Wq, Wk, Wv, Wg);

    // 2) attention: one block per (trunk, head)
    const int smem_bytes = (2 * 64 * 65 + 64 * NKEY) * (int)sizeof(float);  // 98816
    cudaFuncSetAttribute(attn_kernel, cudaFuncAttributeMaxDynamicSharedMemorySize, smem_bytes);
    attn_kernel<<<dim3(NTRUNK, HEADS), 256, smem_bytes>>>(bias);

    // 3) gated output projection
    out_kernel<<<dim3(CDIM / 64, N_TOK / 64), 256>>>(Wo, out);
}

// round 4
// speedup vs baseline: 1.3712x; 1.3712x over previous
#include <cuda_runtime.h>
#include <cuda_bf16.h>
#include <math.h>
#include <stdint.h>

#define N_TOK 4096
#define CDIM 256
#define HEADS 16
#define DHEAD 64
#define HD 1024
#define NQ 64
#define NKEY 256
#define NTRUNK 64
#define PADL 96

// single dynamic-smem declaration (attention kernel only)
extern __shared__ char dyn_smem[];

// ---------------- scratch (device globals; no allocation allowed) ----------
__device__ float g_q[HEADS * N_TOK * DHEAD];   // [h][n][d], pre-scaled 1/sqrt(D)
__device__ float g_k[HEADS * N_TOK * DHEAD];
__device__ float g_v[HEADS * N_TOK * DHEAD];
__device__ float g_gate[N_TOK * HD];
__device__ float g_o[N_TOK * HD];

__device__ __align__(16) __nv_bfloat16 g_aq_hi[N_TOK * CDIM];
__device__ __align__(16) __nv_bfloat16 g_aq_lo[N_TOK * CDIM];
__device__ __align__(16) __nv_bfloat16 g_akv_hi[N_TOK * CDIM];
__device__ __align__(16) __nv_bfloat16 g_akv_lo[N_TOK * CDIM];
__device__ __align__(16) __nv_bfloat16 g_wt_hi[4 * HD * CDIM];   // [mat][n][k]
__device__ __align__(16) __nv_bfloat16 g_wt_lo[4 * HD * CDIM];
__device__ __align__(16) __nv_bfloat16 g_wot_hi[CDIM * HD];      // [n][k]
__device__ __align__(16) __nv_bfloat16 g_wot_lo[CDIM * HD];
__device__ __align__(16) __nv_bfloat16 g_og_hi[N_TOK * HD];
__device__ __align__(16) __nv_bfloat16 g_og_lo[N_TOK * HD];

// ---------------- warp-mma helpers (base PTX ISA, OK at compute_103) -------
__device__ __forceinline__ uint32_t smem_u32(const void* p) {
    uint32_t a;
    asm("{ .reg .u64 t; cvta.to.shared.u64 t, %1; cvt.u32.u64 %0, t; }" : "=r"(a) : "l"(p));
    return a;
}

__device__ __forceinline__ void ldm_x4(uint32_t addr, uint32_t* r) {
    asm volatile("ldmatrix.sync.aligned.m8n8.x4.shared.b16 {%0,%1,%2,%3}, [%4];"
                 : "=r"(r[0]), "=r"(r[1]), "=r"(r[2]), "=r"(r[3]) : "r"(addr));
}

__device__ __forceinline__ void mma16816(float* c, const uint32_t* a, uint32_t b0, uint32_t b1) {
    asm volatile(
        "mma.sync.aligned.m16n8k16.row.col.f32.bf16.bf16.f32 "
        "{%0,%1,%2,%3}, {%4,%5,%6,%7}, {%8,%9}, {%0,%1,%2,%3};"
        : "+f"(c[0]), "+f"(c[1]), "+f"(c[2]), "+f"(c[3])
        : "r"(a[0]), "r"(a[1]), "r"(a[2]), "r"(a[3]), "r"(b0), "r"(b1));
}

// ---------------------------------------------------------------------------
// HMMA GEMM core: acc[4][4][4] (+)= A[128,K] * B[128,K]^T  (bf16x3 split).
// CTA 128x128, 256 threads = 8 warps (2x4 grid of 64x32 warp tiles), BK=32.
// smem rows padded to 40 bf16 (80B) -> conflict-free ldmatrix.
// ---------------------------------------------------------------------------
#define SPITCH 40

__device__ __forceinline__ void gemm_tc(
    const __nv_bfloat16* __restrict__ Ah, const __nv_bfloat16* __restrict__ Al,
    const __nv_bfloat16* __restrict__ Bh, const __nv_bfloat16* __restrict__ Bl,
    int K, float acc[4][4][4])
{
    __shared__ __align__(16) __nv_bfloat16 sAh[128 * SPITCH];
    __shared__ __align__(16) __nv_bfloat16 sAl[128 * SPITCH];
    __shared__ __align__(16) __nv_bfloat16 sBh[128 * SPITCH];
    __shared__ __align__(16) __nv_bfloat16 sBl[128 * SPITCH];

    const int tid = threadIdx.x, lane = tid & 31, warp = tid >> 5;
    const int wm = warp >> 2, wn = warp & 3;
    const int lrow = lane & 15, lcolh = (lane >> 4) * 8;

    for (int kc = 0; kc < K; kc += 32) {
        #pragma unroll
        for (int i = 0; i < 2; i++) {
            int idx = tid + i * 256;
            int r = idx >> 2, g = idx & 3;
            size_t src = (size_t)r * K + kc + g * 8;
            int dst = r * SPITCH + g * 8;
            *(uint4*)&sAh[dst] = *(const uint4*)&Ah[src];
            *(uint4*)&sAl[dst] = *(const uint4*)&Al[src];
            *(uint4*)&sBh[dst] = *(const uint4*)&Bh[src];
            *(uint4*)&sBl[dst] = *(const uint4*)&Bl[src];
        }
        __syncthreads();
        #pragma unroll
        for (int ks = 0; ks < 2; ks++) {
            uint32_t ah[4][4], al[4][4];
            #pragma unroll
            for (int mt = 0; mt < 4; mt++) {
                int ro = (wm * 64 + mt * 16 + lrow) * SPITCH + ks * 16 + lcolh;
                ldm_x4(smem_u32(&sAh[ro]), ah[mt]);
                ldm_x4(smem_u32(&sAl[ro]), al[mt]);
            }
            #pragma unroll
            for (int bt = 0; bt < 2; bt++) {
                uint32_t bh[4], bl[4];
                int ro = (wn * 32 + bt * 16 + lrow) * SPITCH + ks * 16 + lcolh;
                ldm_x4(smem_u32(&sBh[ro]), bh);
                ldm_x4(smem_u32(&sBl[ro]), bl);
                #pragma unroll
                for (int mt = 0; mt < 4; mt++) {
                    mma16816(acc[mt][bt * 2],     ah[mt], bh[0], bh[2]);
                    mma16816(acc[mt][bt * 2],     al[mt], bh[0], bh[2]);
                    mma16816(acc[mt][bt * 2],     ah[mt], bl[0], bl[2]);
                    mma16816(acc[mt][bt * 2 + 1], ah[mt], bh[1], bh[3]);
                    mma16816(acc[mt][bt * 2 + 1], al[mt], bh[1], bh[3]);
                    mma16816(acc[mt][bt * 2 + 1], ah[mt], bl[1], bl[3]);
                }
            }
        }
        __syncthreads();
    }
}

// ---------------------------------------------------------------------------
// conversions
// ---------------------------------------------------------------------------
__global__ __launch_bounds__(256) void conv_act(const float* __restrict__ qx,
                                                const float* __restrict__ kvx)
{
    int idx = blockIdx.x * 256 + threadIdx.x;
    const float* src = blockIdx.y ? kvx : qx;
    __nv_bfloat16* hi = blockIdx.y ? g_akv_hi : g_aq_hi;
    __nv_bfloat16* lo = blockIdx.y ? g_akv_lo : g_aq_lo;
    float x = src[idx];
    __nv_bfloat16 h = __float2bfloat16(x);
    hi[idx] = h;
    lo[idx] = __float2bfloat16(x - __bfloat162float(h));
}

__global__ __launch_bounds__(256) void conv_w(
    const float* __restrict__ Wq, const float* __restrict__ Wk,
    const float* __restrict__ Wv, const float* __restrict__ Wg,
    const float* __restrict__ Wo)
{
    int z = blockIdx.z;
    const float* in; int R, C; __nv_bfloat16 *oh, *ol;
    if (z < 4) {
        in = (z == 0) ? Wq : (z == 1) ? Wk : (z == 2) ? Wv : Wg;
        R = CDIM; C = HD; oh = g_wt_hi + (size_t)z * HD * CDIM; ol = g_wt_lo + (size_t)z * HD * CDIM;
    } else {
        in = Wo; R = HD; C = CDIM; oh = g_wot_hi; ol = g_wot_lo;
    }
    int c0 = blockIdx.x * 32, r0 = blockIdx.y * 32;
    if (c0 >= C || r0 >= R) return;
    __shared__ float t[32][33];
    int tx = threadIdx.x & 31, ty = threadIdx.x >> 5;
    for (int i = ty; i < 32; i += 8) t[i][tx] = in[(size_t)(r0 + i) * C + c0 + tx];
    __syncthreads();
    for (int i = ty; i < 32; i += 8) {
        float x = t[tx][i];
        __nv_bfloat16 h = __float2bfloat16(x);
        size_t o = (size_t)(c0 + i) * R + r0 + tx;
        oh[o] = h;
        ol[o] = __float2bfloat16(x - __bfloat162float(h));
    }
}

__global__ __launch_bounds__(256) void conv_og()
{
    int idx = blockIdx.x * 256 + threadIdx.x;
    float x = g_o[idx] * g_gate[idx];
    __nv_bfloat16 h = __float2bfloat16(x);
    g_og_hi[idx] = h;
    g_og_lo[idx] = __float2bfloat16(x - __bfloat162float(h));
}

// ---------------------------------------------------------------------------
// projection GEMMs: grid (HD/128=8, N_TOK/128=32, 4 mats)
// ---------------------------------------------------------------------------
__global__ __launch_bounds__(256, 2) void mm_proj_tc()
{
    const int mat = blockIdx.z;
    const int m0 = blockIdx.y * 128, n0 = blockIdx.x * 128;
    const __nv_bfloat16* Ah = ((mat == 1 || mat == 2) ? g_akv_hi : g_aq_hi) + (size_t)m0 * CDIM;
    const __nv_bfloat16* Al = ((mat == 1 || mat == 2) ? g_akv_lo : g_aq_lo) + (size_t)m0 * CDIM;
    const __nv_bfloat16* Bh = g_wt_hi + (size_t)mat * HD * CDIM + (size_t)n0 * CDIM;
    const __nv_bfloat16* Bl = g_wt_lo + (size_t)mat * HD * CDIM + (size_t)n0 * CDIM;

    float acc[4][4][4] = {};
    gemm_tc(Ah, Al, Bh, Bl, CDIM, acc);

    const int lane = threadIdx.x & 31, warp = threadIdx.x >> 5;
    const int wm = warp >> 2, wn = warp & 3;
    #pragma unroll
    for (int mt = 0; mt < 4; mt++) {
        #pragma unroll
        for (int nt = 0; nt < 4; nt++) {
            #pragma unroll
            for (int rr = 0; rr < 2; rr++) {
                int m = m0 + wm * 64 + mt * 16 + (lane >> 2) + rr * 8;
                int c = n0 + wn * 32 + nt * 8 + (lane & 3) * 2;
                float v0 = acc[mt][nt][rr * 2], v1 = acc[mt][nt][rr * 2 + 1];
                int h = c >> 6, d = c & 63;
                if (mat == 0) {
                    float2 v = make_float2(v0 * 0.125f, v1 * 0.125f);
                    *(float2*)&g_q[((size_t)h * N_TOK + m) * DHEAD + d] = v;
                } else if (mat == 1) {
                    *(float2*)&g_k[((size_t)h * N_TOK + m) * DHEAD + d] = make_float2(v0, v1);
                } else if (mat == 2) {
                    *(float2*)&g_v[((size_t)h * N_TOK + m) * DHEAD + d] = make_float2(v0, v1);
                } else {
                    float2 v = make_float2(1.f / (1.f + expf(-v0)), 1.f / (1.f + expf(-v1)));
                    *(float2*)&g_gate[(size_t)m * HD + c] = v;
                }
            }
        }
    }
}

// output GEMM: out[4096,256] = og[4096,1024] @ Wo ; grid (2, 32)
__global__ __launch_bounds__(256, 2) void mm_out_tc(float* __restrict__ out)
{
    const int m0 = blockIdx.y * 128, n0 = blockIdx.x * 128;
    float acc[4][4][4] = {};
    gemm_tc(g_og_hi + (size_t)m0 * HD, g_og_lo + (size_t)m0 * HD,
            g_wot_hi + (size_t)n0 * HD, g_wot_lo + (size_t)n0 * HD, HD, acc);

    const int lane = threadIdx.x & 31, warp = threadIdx.x >> 5;
    const int wm = warp >> 2, wn = warp & 3;
    #pragma unroll
    for (int mt = 0; mt < 4; mt++) {
        #pragma unroll
        for (int nt = 0; nt < 4; nt++) {
            #pragma unroll
            for (int rr = 0; rr < 2; rr++) {
                int m = m0 + wm * 64 + mt * 16 + (lane >> 2) + rr * 8;
                int c = n0 + wn * 32 + nt * 8 + (lane & 3) * 2;
                *(float2*)&out[(size_t)m * CDIM + c] =
                    make_float2(acc[mt][nt][rr * 2], acc[mt][nt][rr * 2 + 1]);
            }
        }
    }
}

// ---------------------------------------------------------------------------
// local attention (fp32, unchanged logic)
// ---------------------------------------------------------------------------
__global__ __launch_bounds__(256) void attn_kernel(const float* __restrict__ bias)
{
    float* smem = (float*)dyn_smem;
    float (*qs)[65] = (float(*)[65])smem;
    float (*ks)[65] = (float(*)[65])(smem + 64 * 65);
    float (*sc)[NKEY] = (float(*)[NKEY])(smem + 2 * 64 * 65);

    const int t = blockIdx.x, h = blockIdx.y;
    const int tid = threadIdx.x;
    const int tx = tid & 15, ty = tid >> 4;
    const int kbase = t * NQ - PADL;

    const float* qsrc = &g_q[(size_t)h * N_TOK * DHEAD + (size_t)t * NQ * DHEAD];
    for (int i = tid; i < NQ * DHEAD; i += 256) qs[i / DHEAD][i % DHEAD] = qsrc[i];

    for (int kc = 0; kc < 4; kc++) {
        __syncthreads();
        for (int i = tid; i < 64 * DHEAD; i += 256) {
            int jj = i / DHEAD, d = i % DHEAD;
            int gk = kbase + kc * 64 + jj;
            ks[jj][d] = (gk >= 0 && gk < N_TOK) ? g_k[(size_t)h * N_TOK * DHEAD + (size_t)gk * DHEAD + d] : 0.f;
        }
        __syncthreads();
        float acc[4][4] = {};
        #pragma unroll 16
        for (int d = 0; d < DHEAD; d++) {
            float aq[4], ak[4];
            #pragma unroll
            for (int i = 0; i < 4; i++) aq[i] = qs[ty * 4 + i][d];
            #pragma unroll
            for (int j = 0; j < 4; j++) ak[j] = ks[tx * 4 + j][d];
            #pragma unroll
            for (int i = 0; i < 4; i++)
                #pragma unroll
                for (int j = 0; j < 4; j++) acc[i][j] += aq[i] * ak[j];
        }
        #pragma unroll
        for (int i = 0; i < 4; i++) {
            int qi = ty * 4 + i;
            #pragma unroll
            for (int j = 0; j < 4; j++) {
                int jj = tx * 4 + j;
                int gk = kbase + kc * 64 + jj;
                float b = (gk >= 0 && gk < N_TOK)
                        ? bias[(size_t)(t * NQ + qi) * N_TOK + gk] : 0.f;
                sc[qi][kc * 64 + jj] = acc[i][j] + b;
            }
        }
    }
    __syncthreads();

    const int wid = tid >> 5, lane = tid & 31;
    for (int r = wid; r < NQ; r += 8) {
        float vals[8];
        float m = -1e30f;
        #pragma unroll
        for (int k = 0; k < 8; k++) { vals[k] = sc[r][lane + 32 * k]; m = fmaxf(m, vals[k]); }
        #pragma unroll
        for (int off = 16; off > 0; off >>= 1) m = fmaxf(m, __shfl_xor_sync(0xffffffffu, m, off));
        float s = 0.f;
        #pragma unroll
        for (int k = 0; k < 8; k++) { vals[k] = expf(vals[k] - m); s += vals[k]; }
        #pragma unroll
        for (int off = 16; off > 0; off >>= 1) s += __shfl_xor_sync(0xffffffffu, s, off);
        float inv = 1.f / s;
        #pragma unroll
        for (int k = 0; k < 8; k++) sc[r][lane + 32 * k] = vals[k] * inv;
    }
    __syncthreads();

    float oacc[4][4] = {};
    for (int kc = 0; kc < 4; kc++) {
        for (int i = tid; i < 64 * DHEAD; i += 256) {
            int jj = i / DHEAD, d = i % DHEAD;
            int gk = kbase + kc * 64 + jj;
            ks[jj][d] = (gk >= 0 && gk < N_TOK) ? g_v[(size_t)h * N_TOK * DHEAD + (size_t)gk * DHEAD + d] : 0.f;
        }
        __syncthreads();
        #pragma unroll 16
        for (int jj = 0; jj < 64; jj++) {
            float w[4], vv[4];
            #pragma unroll
            for (int i = 0; i < 4; i++) w[i] = sc[ty * 4 + i][kc * 64 + jj];
            #pragma unroll
            for (int j = 0; j < 4; j++) vv[j] = ks[jj][tx * 4 + j];
            #pragma unroll
            for (int i = 0; i < 4; i++)
                #pragma unroll
                for (int j = 0; j < 4; j++) oacc[i][j] += w[i] * vv[j];
        }
        __syncthreads();
    }

    #pragma unroll
    for (int i = 0; i < 4; i++) {
        int r = t * NQ + ty * 4 + i;
        #pragma unroll
        for (int j = 0; j < 4; j++)
            g_o[(size_t)r * HD + h * DHEAD + tx * 4 + j] = oacc[i][j];
    }
}

// ---------------------------------------------------------------------------
extern "C" void kernel_launch(void* const* d_in, const int* in_sizes, int n_in,
                              void* d_out, int out_size)
{
    const float* qx   = (const float*)d_in[0];
    const float* kvx  = (const float*)d_in[1];
    const float* bias = (const float*)d_in[2];
    const float* Wq   = (const float*)d_in[3];
    const float* Wk   = (const float*)d_in[4];
    const float* Wv   = (const float*)d_in[5];
    const float* Wg   = (const float*)d_in[6];
    const float* Wo   = (const float*)d_in[7];
    float* out = (float*)d_out;

    static int configured = 0;
    if (!configured) {
        cudaFuncSetAttribute(attn_kernel, cudaFuncAttributeMaxDynamicSharedMemorySize,
                             (2 * 64 * 65 + 64 * NKEY) * (int)sizeof(float));
        configured = 1;
    }

    // 1) convert activations + weights to bf16 hi/lo (weights transposed)
    conv_act<<<dim3(N_TOK * CDIM / 256, 2), 256>>>(qx, kvx);
    conv_w<<<dim3(32, 32, 5), 256>>>(Wq, Wk, Wv, Wg, Wo);

    // 2) q/k/v/gate projections on tensor cores (mma.sync bf16x3)
    mm_proj_tc<<<dim3(HD / 128, N_TOK / 128, 4), 256>>>();

    // 3) local attention (fp32)
    const int smem_attn = (2 * 64 * 65 + 64 * NKEY) * (int)sizeof(float);
    attn_kernel<<<dim3(NTRUNK, HEADS), 256, smem_attn>>>(bias);

    // 4) gate-multiply + convert, then output GEMM on tensor cores
    conv_og<<<N_TOK * HD / 256, 256>>>();
    mm_out_tc<<<dim3(CDIM / 128, N_TOK / 128), 256>>>(out);
}

// round 5
// speedup vs baseline: 1.9180x; 1.3988x over previous
#include <cuda_runtime.h>
#include <cuda_bf16.h>
#include <math.h>
#include <stdint.h>

#define N_TOK 4096
#define CDIM 256
#define HEADS 16
#define DHEAD 64
#define HD 1024
#define NQ 64
#define NKEY 256
#define NTRUNK 64
#define PADL 96

extern __shared__ char dyn_smem[];

// ---------------- scratch (device globals) ----------------
__device__ float g_gate[N_TOK * HD];
__device__ float g_o[N_TOK * HD];

__device__ __align__(16) __nv_bfloat16 g_aq_hi[N_TOK * CDIM];
__device__ __align__(16) __nv_bfloat16 g_aq_lo[N_TOK * CDIM];
__device__ __align__(16) __nv_bfloat16 g_akv_hi[N_TOK * CDIM];
__device__ __align__(16) __nv_bfloat16 g_akv_lo[N_TOK * CDIM];
__device__ __align__(16) __nv_bfloat16 g_wt_hi[4 * HD * CDIM];   // [mat][n][k]
__device__ __align__(16) __nv_bfloat16 g_wt_lo[4 * HD * CDIM];
__device__ __align__(16) __nv_bfloat16 g_wot_hi[CDIM * HD];      // [n][k]
__device__ __align__(16) __nv_bfloat16 g_wot_lo[CDIM * HD];
__device__ __align__(16) __nv_bfloat16 g_og_hi[N_TOK * HD];
__device__ __align__(16) __nv_bfloat16 g_og_lo[N_TOK * HD];

// attention operands (bf16 hi/lo), q pre-scaled by 1/8
__device__ __align__(16) __nv_bfloat16 g_qh[HEADS * N_TOK * DHEAD];  // [h][n][d]
__device__ __align__(16) __nv_bfloat16 g_ql[HEADS * N_TOK * DHEAD];
__device__ __align__(16) __nv_bfloat16 g_kh[HEADS * N_TOK * DHEAD];  // [h][n][d]
__device__ __align__(16) __nv_bfloat16 g_kl[HEADS * N_TOK * DHEAD];
__device__ __align__(16) __nv_bfloat16 g_vth[HEADS * DHEAD * N_TOK]; // [h][d][n]
__device__ __align__(16) __nv_bfloat16 g_vtl[HEADS * DHEAD * N_TOK];

// ---------------- warp-mma helpers (base PTX ISA) -------
__device__ __forceinline__ uint32_t smem_u32(const void* p) {
    uint32_t a;
    asm("{ .reg .u64 t; cvta.to.shared.u64 t, %1; cvt.u32.u64 %0, t; }" : "=r"(a) : "l"(p));
    return a;
}

__device__ __forceinline__ void ldm_x4(uint32_t addr, uint32_t* r) {
    asm volatile("ldmatrix.sync.aligned.m8n8.x4.shared.b16 {%0,%1,%2,%3}, [%4];"
                 : "=r"(r[0]), "=r"(r[1]), "=r"(r[2]), "=r"(r[3]) : "r"(addr));
}

__device__ __forceinline__ void mma16816(float* c, const uint32_t* a, uint32_t b0, uint32_t b1) {
    asm volatile(
        "mma.sync.aligned.m16n8k16.row.col.f32.bf16.bf16.f32 "
        "{%0,%1,%2,%3}, {%4,%5,%6,%7}, {%8,%9}, {%0,%1,%2,%3};"
        : "+f"(c[0]), "+f"(c[1]), "+f"(c[2]), "+f"(c[3])
        : "r"(a[0]), "r"(a[1]), "r"(a[2]), "r"(a[3]), "r"(b0), "r"(b1));
}

__device__ __forceinline__ uint32_t pack_bf16x2(float x0, float x1) {
    __nv_bfloat162 p;
    p.x = __float2bfloat16(x0);
    p.y = __float2bfloat16(x1);
    return *(uint32_t*)&p;
}

// ---------------------------------------------------------------------------
// dense GEMM core (CTA 128x128, BK=32, 8 warps 64x32, bf16x3)
// ---------------------------------------------------------------------------
#define SPITCH 40

__device__ __forceinline__ void gemm_tc(
    const __nv_bfloat16* __restrict__ Ah, const __nv_bfloat16* __restrict__ Al,
    const __nv_bfloat16* __restrict__ Bh, const __nv_bfloat16* __restrict__ Bl,
    int K, float acc[4][4][4])
{
    __shared__ __align__(16) __nv_bfloat16 sAh[128 * SPITCH];
    __shared__ __align__(16) __nv_bfloat16 sAl[128 * SPITCH];
    __shared__ __align__(16) __nv_bfloat16 sBh[128 * SPITCH];
    __shared__ __align__(16) __nv_bfloat16 sBl[128 * SPITCH];

    const int tid = threadIdx.x, lane = tid & 31, warp = tid >> 5;
    const int wm = warp >> 2, wn = warp & 3;
    const int lrow = lane & 15, lcolh = (lane >> 4) * 8;

    for (int kc = 0; kc < K; kc += 32) {
        #pragma unroll
        for (int i = 0; i < 2; i++) {
            int idx = tid + i * 256;
            int r = idx >> 2, g = idx & 3;
            size_t src = (size_t)r * K + kc + g * 8;
            int dst = r * SPITCH + g * 8;
            *(uint4*)&sAh[dst] = *(const uint4*)&Ah[src];
            *(uint4*)&sAl[dst] = *(const uint4*)&Al[src];
            *(uint4*)&sBh[dst] = *(const uint4*)&Bh[src];
            *(uint4*)&sBl[dst] = *(const uint4*)&Bl[src];
        }
        __syncthreads();
        #pragma unroll
        for (int ks = 0; ks < 2; ks++) {
            uint32_t ah[4][4], al[4][4];
            #pragma unroll
            for (int mt = 0; mt < 4; mt++) {
                int ro = (wm * 64 + mt * 16 + lrow) * SPITCH + ks * 16 + lcolh;
                ldm_x4(smem_u32(&sAh[ro]), ah[mt]);
                ldm_x4(smem_u32(&sAl[ro]), al[mt]);
            }
            #pragma unroll
            for (int bt = 0; bt < 2; bt++) {
                uint32_t bh[4], bl[4];
                int ro = (wn * 32 + bt * 16 + lrow) * SPITCH + ks * 16 + lcolh;
                ldm_x4(smem_u32(&sBh[ro]), bh);
                ldm_x4(smem_u32(&sBl[ro]), bl);
                #pragma unroll
                for (int mt = 0; mt < 4; mt++) {
                    mma16816(acc[mt][bt * 2],     ah[mt], bh[0], bh[2]);
                    mma16816(acc[mt][bt * 2],     al[mt], bh[0], bh[2]);
                    mma16816(acc[mt][bt * 2],     ah[mt], bl[0], bl[2]);
                    mma16816(acc[mt][bt * 2 + 1], ah[mt], bh[1], bh[3]);
                    mma16816(acc[mt][bt * 2 + 1], al[mt], bh[1], bh[3]);
                    mma16816(acc[mt][bt * 2 + 1], ah[mt], bl[1], bl[3]);
                }
            }
        }
        __syncthreads();
    }
}

// ---------------------------------------------------------------------------
// conversions
// ---------------------------------------------------------------------------
__global__ __launch_bounds__(256) void conv_act(const float* __restrict__ qx,
                                                const float* __restrict__ kvx)
{
    int idx = blockIdx.x * 256 + threadIdx.x;
    const float* src = blockIdx.y ? kvx : qx;
    __nv_bfloat16* hi = blockIdx.y ? g_akv_hi : g_aq_hi;
    __nv_bfloat16* lo = blockIdx.y ? g_akv_lo : g_aq_lo;
    float x = src[idx];
    __nv_bfloat16 h = __float2bfloat16(x);
    hi[idx] = h;
    lo[idx] = __float2bfloat16(x - __bfloat162float(h));
}

__global__ __launch_bounds__(256) void conv_w(
    const float* __restrict__ Wq, const float* __restrict__ Wk,
    const float* __restrict__ Wv, const float* __restrict__ Wg,
    const float* __restrict__ Wo)
{
    int z = blockIdx.z;
    const float* in; int R, C; __nv_bfloat16 *oh, *ol;
    if (z < 4) {
        in = (z == 0) ? Wq : (z == 1) ? Wk : (z == 2) ? Wv : Wg;
        R = CDIM; C = HD; oh = g_wt_hi + (size_t)z * HD * CDIM; ol = g_wt_lo + (size_t)z * HD * CDIM;
    } else {
        in = Wo; R = HD; C = CDIM; oh = g_wot_hi; ol = g_wot_lo;
    }
    int c0 = blockIdx.x * 32, r0 = blockIdx.y * 32;
    if (c0 >= C || r0 >= R) return;
    __shared__ float t[32][33];
    int tx = threadIdx.x & 31, ty = threadIdx.x >> 5;
    for (int i = ty; i < 32; i += 8) t[i][tx] = in[(size_t)(r0 + i) * C + c0 + tx];
    __syncthreads();
    for (int i = ty; i < 32; i += 8) {
        float x = t[tx][i];
        __nv_bfloat16 h = __float2bfloat16(x);
        size_t o = (size_t)(c0 + i) * R + r0 + tx;
        oh[o] = h;
        ol[o] = __float2bfloat16(x - __bfloat162float(h));
    }
}

__global__ __launch_bounds__(256) void conv_og()
{
    int idx = blockIdx.x * 256 + threadIdx.x;
    float x = g_o[idx] * g_gate[idx];
    __nv_bfloat16 h = __float2bfloat16(x);
    g_og_hi[idx] = h;
    g_og_lo[idx] = __float2bfloat16(x - __bfloat162float(h));
}

// ---------------------------------------------------------------------------
// projection GEMMs: grid (HD/128=8, N_TOK/128=32, 4 mats)
// epilogue writes q/k bf16 hi/lo [h][n][d], v TRANSPOSED bf16 hi/lo [h][d][n],
// gate fp32.
// ---------------------------------------------------------------------------
__global__ __launch_bounds__(256, 2) void mm_proj_tc()
{
    const int mat = blockIdx.z;
    const int m0 = blockIdx.y * 128, n0 = blockIdx.x * 128;
    const __nv_bfloat16* Ah = ((mat == 1 || mat == 2) ? g_akv_hi : g_aq_hi) + (size_t)m0 * CDIM;
    const __nv_bfloat16* Al = ((mat == 1 || mat == 2) ? g_akv_lo : g_aq_lo) + (size_t)m0 * CDIM;
    const __nv_bfloat16* Bh = g_wt_hi + (size_t)mat * HD * CDIM + (size_t)n0 * CDIM;
    const __nv_bfloat16* Bl = g_wt_lo + (size_t)mat * HD * CDIM + (size_t)n0 * CDIM;

    float acc[4][4][4] = {};
    gemm_tc(Ah, Al, Bh, Bl, CDIM, acc);

    const int lane = threadIdx.x & 31, warp = threadIdx.x >> 5;
    const int wm = warp >> 2, wn = warp & 3;
    #pragma unroll
    for (int mt = 0; mt < 4; mt++) {
        #pragma unroll
        for (int nt = 0; nt < 4; nt++) {
            #pragma unroll
            for (int rr = 0; rr < 2; rr++) {
                int m = m0 + wm * 64 + mt * 16 + (lane >> 2) + rr * 8;
                int c = n0 + wn * 32 + nt * 8 + (lane & 3) * 2;
                float v0 = acc[mt][nt][rr * 2], v1 = acc[mt][nt][rr * 2 + 1];
                int hh = c >> 6, d = c & 63;
                if (mat == 0) {
                    float x0 = v0 * 0.125f, x1 = v1 * 0.125f;
                    __nv_bfloat16 b0 = __float2bfloat16(x0), b1 = __float2bfloat16(x1);
                    __nv_bfloat162 ph; ph.x = b0; ph.y = b1;
                    __nv_bfloat162 pl;
                    pl.x = __float2bfloat16(x0 - __bfloat162float(b0));
                    pl.y = __float2bfloat16(x1 - __bfloat162float(b1));
                    size_t o = ((size_t)hh * N_TOK + m) * DHEAD + d;
                    *(__nv_bfloat162*)&g_qh[o] = ph;
                    *(__nv_bfloat162*)&g_ql[o] = pl;
                } else if (mat == 1) {
                    __nv_bfloat16 b0 = __float2bfloat16(v0), b1 = __float2bfloat16(v1);
                    __nv_bfloat162 ph; ph.x = b0; ph.y = b1;
                    __nv_bfloat162 pl;
                    pl.x = __float2bfloat16(v0 - __bfloat162float(b0));
                    pl.y = __float2bfloat16(v1 - __bfloat162float(b1));
                    size_t o = ((size_t)hh * N_TOK + m) * DHEAD + d;
                    *(__nv_bfloat162*)&g_kh[o] = ph;
                    *(__nv_bfloat162*)&g_kl[o] = pl;
                } else if (mat == 2) {
                    __nv_bfloat16 b0 = __float2bfloat16(v0), b1 = __float2bfloat16(v1);
                    size_t o0 = ((size_t)hh * DHEAD + d) * N_TOK + m;
                    size_t o1 = ((size_t)hh * DHEAD + d + 1) * N_TOK + m;
                    g_vth[o0] = b0;
                    g_vth[o1] = b1;
                    g_vtl[o0] = __float2bfloat16(v0 - __bfloat162float(b0));
                    g_vtl[o1] = __float2bfloat16(v1 - __bfloat162float(b1));
                } else {
                    float2 v = make_float2(1.f / (1.f + expf(-v0)), 1.f / (1.f + expf(-v1)));
                    *(float2*)&g_gate[(size_t)m * HD + c] = v;
                }
            }
        }
    }
}

// output GEMM
__global__ __launch_bounds__(256, 2) void mm_out_tc(float* __restrict__ out)
{
    const int m0 = blockIdx.y * 128, n0 = blockIdx.x * 128;
    float acc[4][4][4] = {};
    gemm_tc(g_og_hi + (size_t)m0 * HD, g_og_lo + (size_t)m0 * HD,
            g_wot_hi + (size_t)n0 * HD, g_wot_lo + (size_t)n0 * HD, HD, acc);

    const int lane = threadIdx.x & 31, warp = threadIdx.x >> 5;
    const int wm = warp >> 2, wn = warp & 3;
    #pragma unroll
    for (int mt = 0; mt < 4; mt++) {
        #pragma unroll
        for (int nt = 0; nt < 4; nt++) {
            #pragma unroll
            for (int rr = 0; rr < 2; rr++) {
                int m = m0 + wm * 64 + mt * 16 + (lane >> 2) + rr * 8;
                int c = n0 + wn * 32 + nt * 8 + (lane & 3) * 2;
                *(float2*)&out[(size_t)m * CDIM + c] =
                    make_float2(acc[mt][nt][rr * 2], acc[mt][nt][rr * 2 + 1]);
            }
        }
    }
}

// ---------------------------------------------------------------------------
// tensor-core local attention. Block = (head, trunk), 256 threads = 8 warps.
// Warp layout: wm = warp&3 -> 16 query rows; ch = warp>>2 -> 128-key half.
// smem (bf16 units): sQh 0..4608, sQl ..9216, sKh 9216..27648, sKl ..46080;
// sVh overlays 9216..26112, sVl 26112..43008; pm/ps floats at byte 92160.
// sO (fp32 O-combine) overlays the Q region. Total 93184 B.
// ---------------------------------------------------------------------------
#define QP 72
#define VP 264

__global__ __launch_bounds__(256) void attn_tc(const float* __restrict__ bias)
{
    __nv_bfloat16* Sb = (__nv_bfloat16*)dyn_smem;
    __nv_bfloat16* sQh = Sb;
    __nv_bfloat16* sQl = Sb + 4608;
    __nv_bfloat16* sKh = Sb + 9216;
    __nv_bfloat16* sKl = Sb + 27648;
    __nv_bfloat16* sVh = Sb + 9216;
    __nv_bfloat16* sVl = Sb + 26112;
    float* sO = (float*)dyn_smem;
    float* pm = (float*)(dyn_smem + 92160);
    float* ps = (float*)(dyn_smem + 92672);

    const int h = blockIdx.x, t = blockIdx.y;
    const int tid = threadIdx.x, lane = tid & 31, warp = tid >> 5;
    const int wm = warp & 3, ch = warp >> 2;
    const int kbase = t * NQ - PADL;
    const int lrow = lane & 15, lcolh = (lane >> 4) * 8;
    const int l4 = lane >> 2, lq = lane & 3;

    // ---- load Q (64x64) and K (256x64), hi/lo, zero-padding OOB keys ----
    {
        const __nv_bfloat16* qh = g_qh + ((size_t)h * N_TOK + t * NQ) * DHEAD;
        const __nv_bfloat16* ql = g_ql + ((size_t)h * N_TOK + t * NQ) * DHEAD;
        #pragma unroll
        for (int i = 0; i < 2; i++) {
            int idx = tid + i * 256;
            int r = idx >> 3, g = idx & 7;
            *(uint4*)&sQh[r * QP + g * 8] = *(const uint4*)&qh[idx * 8];
            *(uint4*)&sQl[r * QP + g * 8] = *(const uint4*)&ql[idx * 8];
        }
        #pragma unroll
        for (int i = 0; i < 8; i++) {
            int idx = tid + i * 256;
            int r = idx >> 3, g = idx & 7;
            int gk = kbase + r;
            uint4 vh = {0, 0, 0, 0}, vl = {0, 0, 0, 0};
            if (gk >= 0 && gk < N_TOK) {
                size_t src = ((size_t)h * N_TOK + gk) * DHEAD + g * 8;
                vh = *(const uint4*)&g_kh[src];
                vl = *(const uint4*)&g_kl[src];
            }
            *(uint4*)&sKh[r * QP + g * 8] = vh;
            *(uint4*)&sKl[r * QP + g * 8] = vl;
        }
    }
    __syncthreads();

    // ---- S = Q K^T (bf16x3) : warp computes 16 rows x 128 keys ----
    uint32_t ah[4][4], al[4][4];
    #pragma unroll
    for (int kc = 0; kc < 4; kc++) {
        int ro = (wm * 16 + lrow) * QP + kc * 16 + lcolh;
        ldm_x4(smem_u32(&sQh[ro]), ah[kc]);
        ldm_x4(smem_u32(&sQl[ro]), al[kc]);
    }
    float acc[16][4];
    #pragma unroll
    for (int i = 0; i < 16; i++) { acc[i][0] = 0.f; acc[i][1] = 0.f; acc[i][2] = 0.f; acc[i][3] = 0.f; }
    #pragma unroll
    for (int nt = 0; nt < 8; nt++) {
        #pragma unroll
        for (int kc = 0; kc < 4; kc++) {
            uint32_t bh[4], bl[4];
            int ro = (ch * 128 + nt * 16 + lrow) * QP + kc * 16 + lcolh;
            ldm_x4(smem_u32(&sKh[ro]), bh);
            ldm_x4(smem_u32(&sKl[ro]), bl);
            mma16816(acc[2 * nt],     ah[kc], bh[0], bh[2]);
            mma16816(acc[2 * nt],     al[kc], bh[0], bh[2]);
            mma16816(acc[2 * nt],     ah[kc], bl[0], bl[2]);
            mma16816(acc[2 * nt + 1], ah[kc], bh[1], bh[3]);
            mma16816(acc[2 * nt + 1], al[kc], bh[1], bh[3]);
            mma16816(acc[2 * nt + 1], ah[kc], bl[1], bl[3]);
        }
    }

    // ---- add bias (OOB keys keep score exactly 0) ----
    {
        const int r0 = t * NQ + wm * 16 + l4;
        const int c0 = kbase + ch * 128 + lq * 2;
        #pragma unroll
        for (int nt = 0; nt < 16; nt++) {
            int gc = c0 + nt * 8;
            if (gc >= 0 && gc < N_TOK) {
                float2 b0 = *(const float2*)&bias[(size_t)r0 * N_TOK + gc];
                float2 b1 = *(const float2*)&bias[(size_t)(r0 + 8) * N_TOK + gc];
                acc[nt][0] += b0.x; acc[nt][1] += b0.y;
                acc[nt][2] += b1.x; acc[nt][3] += b1.y;
            }
        }
    }

    // ---- softmax (register fragments + cross-half combine) ----
    const int rloc = wm * 16 + l4;
    float mx0 = -1e30f, mx1 = -1e30f;
    #pragma unroll
    for (int nt = 0; nt < 16; nt++) {
        mx0 = fmaxf(mx0, fmaxf(acc[nt][0], acc[nt][1]));
        mx1 = fmaxf(mx1, fmaxf(acc[nt][2], acc[nt][3]));
    }
    mx0 = fmaxf(mx0, __shfl_xor_sync(0xffffffffu, mx0, 1));
    mx0 = fmaxf(mx0, __shfl_xor_sync(0xffffffffu, mx0, 2));
    mx1 = fmaxf(mx1, __shfl_xor_sync(0xffffffffu, mx1, 1));
    mx1 = fmaxf(mx1, __shfl_xor_sync(0xffffffffu, mx1, 2));
    if (lq == 0) { pm[ch * 64 + rloc] = mx0; pm[ch * 64 + rloc + 8] = mx1; }
    __syncthreads();   // pm ready; all S mmas done -> safe to overwrite K with V

    float M0 = fmaxf(pm[rloc], pm[64 + rloc]);
    float M1 = fmaxf(pm[rloc + 8], pm[64 + rloc + 8]);
    float s0 = 0.f, s1 = 0.f;
    #pragma unroll
    for (int nt = 0; nt < 16; nt++) {
        acc[nt][0] = __expf(acc[nt][0] - M0); s0 += acc[nt][0];
        acc[nt][1] = __expf(acc[nt][1] - M0); s0 += acc[nt][1];
        acc[nt][2] = __expf(acc[nt][2] - M1); s1 += acc[nt][2];
        acc[nt][3] = __expf(acc[nt][3] - M1); s1 += acc[nt][3];
    }
    s0 += __shfl_xor_sync(0xffffffffu, s0, 1);
    s0 += __shfl_xor_sync(0xffffffffu, s0, 2);
    s1 += __shfl_xor_sync(0xffffffffu, s1, 1);
    s1 += __shfl_xor_sync(0xffffffffu, s1, 2);
    if (lq == 0) { ps[ch * 64 + rloc] = s0; ps[ch * 64 + rloc + 8] = s1; }

    // ---- cooperative V^T load (overlays K region) ----
    #pragma unroll
    for (int i = 0; i < 8; i++) {
        int idx = tid + i * 256;            // 64 d-rows x 32 groups of 8 keys
        int d = idx >> 5, g = idx & 31;
        int gk0 = kbase + g * 8;
        uint4 vh = {0, 0, 0, 0}, vl = {0, 0, 0, 0};
        if (gk0 >= 0 && gk0 < N_TOK) {
            size_t src = ((size_t)h * DHEAD + d) * N_TOK + gk0;
            vh = *(const uint4*)&g_vth[src];
            vl = *(const uint4*)&g_vtl[src];
        }
        *(uint4*)&sVh[d * VP + g * 8] = vh;
        *(uint4*)&sVl[d * VP + g * 8] = vl;
    }
    __syncthreads();   // ps ready + V ready

    float inv0 = 1.f / (ps[rloc] + ps[64 + rloc]);
    float inv1 = 1.f / (ps[rloc + 8] + ps[64 + rloc + 8]);
    #pragma unroll
    for (int nt = 0; nt < 16; nt++) {
        acc[nt][0] *= inv0; acc[nt][1] *= inv0;
        acc[nt][2] *= inv1; acc[nt][3] *= inv1;
    }

    // ---- O = W V  (W fragments repacked from acc; split-k over key halves) ----
    float oacc[8][4];
    #pragma unroll
    for (int i = 0; i < 8; i++) { oacc[i][0] = 0.f; oacc[i][1] = 0.f; oacc[i][2] = 0.f; oacc[i][3] = 0.f; }
    #pragma unroll
    for (int kc = 0; kc < 8; kc++) {
        uint32_t awh[4], awl[4];
        #pragma unroll
        for (int f = 0; f < 4; f++) {
            int nt = 2 * kc + (f >> 1);
            int j = (f & 1) * 2;
            float x0 = acc[nt][j], x1 = acc[nt][j + 1];
            __nv_bfloat16 b0 = __float2bfloat16(x0), b1 = __float2bfloat16(x1);
            __nv_bfloat162 ph; ph.x = b0; ph.y = b1;
            awh[f] = *(uint32_t*)&ph;
            awl[f] = pack_bf16x2(x0 - __bfloat162float(b0), x1 - __bfloat162float(b1));
        }
        #pragma unroll
        for (int dg = 0; dg < 4; dg++) {
            uint32_t bh[4], bl[4];
            int ro = (dg * 16 + lrow) * VP + ch * 128 + kc * 16 + lcolh;
            ldm_x4(smem_u32(&sVh[ro]), bh);
            ldm_x4(smem_u32(&sVl[ro]), bl);
            mma16816(oacc[2 * dg],     awh, bh[0], bh[2]);
            mma16816(oacc[2 * dg],     awl, bh[0], bh[2]);
            mma16816(oacc[2 * dg],     awh, bl[0], bl[2]);
            mma16816(oacc[2 * dg + 1], awh, bh[1], bh[3]);
            mma16816(oacc[2 * dg + 1], awl, bh[1], bh[3]);
            mma16816(oacc[2 * dg + 1], awh, bl[1], bl[3]);
        }
    }

    // ---- combine the two key-half partial O's, write g_o fp32 ----
    __syncthreads();   // Q region dead; V reads done
    if (ch == 1) {
        #pragma unroll
        for (int nt = 0; nt < 8; nt++) {
            int c = nt * 8 + lq * 2;
            sO[(wm * 16 + l4) * 66 + c] = oacc[nt][0];
            sO[(wm * 16 + l4) * 66 + c + 1] = oacc[nt][1];
            sO[(wm * 16 + l4 + 8) * 66 + c] = oacc[nt][2];
            sO[(wm * 16 + l4 + 8) * 66 + c + 1] = oacc[nt][3];
        }
    }
    __syncthreads();
    if (ch == 0) {
        #pragma unroll
        for (int nt = 0; nt < 8; nt++) {
            int r = wm * 16 + l4, c = nt * 8 + lq * 2;
            float2 v0 = make_float2(oacc[nt][0] + sO[r * 66 + c],
                                    oacc[nt][1] + sO[r * 66 + c + 1]);
            float2 v1 = make_float2(oacc[nt][2] + sO[(r + 8) * 66 + c],
                                    oacc[nt][3] + sO[(r + 8) * 66 + c + 1]);
            *(float2*)&g_o[(size_t)(t * NQ + r) * HD + h * DHEAD + c] = v0;
            *(float2*)&g_o[(size_t)(t * NQ + r + 8) * HD + h * DHEAD + c] = v1;
        }
    }
}

// ---------------------------------------------------------------------------
extern "C" void kernel_launch(void* const* d_in, const int* in_sizes, int n_in,
                              void* d_out, int out_size)
{
    const float* qx   = (const float*)d_in[0];
    const float* kvx  = (const float*)d_in[1];
    const float* bias = (const float*)d_in[2];
    const float* Wq   = (const float*)d_in[3];
    const float* Wk   = (const float*)d_in[4];
    const float* Wv   = (const float*)d_in[5];
    const float* Wg   = (const float*)d_in[6];
    const float* Wo   = (const float*)d_in[7];
    float* out = (float*)d_out;

    static int configured = 0;
    if (!configured) {
        cudaFuncSetAttribute(attn_tc, cudaFuncAttributeMaxDynamicSharedMemorySize, 93184);
        configured = 1;
    }

    conv_act<<<dim3(N_TOK * CDIM / 256, 2), 256>>>(qx, kvx);
    conv_w<<<dim3(32, 32, 5), 256>>>(Wq, Wk, Wv, Wg, Wo);

    mm_proj_tc<<<dim3(HD / 128, N_TOK / 128, 4), 256>>>();

    attn_tc<<<dim3(HEADS, NTRUNK), 256, 93184>>>(bias);

    conv_og<<<N_TOK * HD / 256, 256>>>();
    mm_out_tc<<<dim3(CDIM / 128, N_TOK / 128), 256>>>(out);
}